// round 16
// baseline (speedup 1.0000x reference)
#include <cuda_runtime.h>
#include <cuda_bf16.h>

#define TPB    64          // 32 rows/block; even lane = pred, odd lane = gt
#define ROWS_B 32
#define ROWF   60
#define STR    33          // smem row stride (odd -> conflict-free)
#define GTOFF  (ROWS_B * STR + 16)   // +16: lane pairs hit disjoint bank halves
#define NSTEP  10

__device__ float        g_partials[8192];
__device__ unsigned int g_count = 0;

// ---------------------------------------------------------------------------
// fast atan2: degree-7 minimax, max abs err ~6e-4 rad. Validated R12-R15:
// loss rel_err bit-identical (7.56e-7) vs degree-9 — far under the 1e-3 gate.
// ---------------------------------------------------------------------------
__device__ __forceinline__ float atan_core(float a) {   // a in [0,1]
    float s  = a * a;
    float r  = fmaf(0.079331f, s, -0.288679f);
    r = fmaf(r, s, 0.995354f);
    return a * r;
}

__device__ __forceinline__ float fast_atan2f(float y, float x) {
    float ax = fabsf(x), ay = fabsf(y);
    float mx = fmaxf(ax, ay);
    float mn = fminf(ax, ay);
    float r  = atan_core(__fdividef(mn, mx));
    if (ay > ax)   r = 1.57079632679489662f - r;
    if (x < 0.0f)  r = 3.14159265358979323f - r;
    return copysignf(r, y);
}

// x >= 0 guaranteed
__device__ __forceinline__ float fast_atan2_posx(float y, float x) {
    float ay = fabsf(y);
    float mx = fmaxf(x, ay);
    float mn = fminf(x, ay);
    float r  = atan_core(__fdividef(mn, mx));
    if (ay > x) r = 1.57079632679489662f - r;
    return copysignf(r, y);
}

// only 5 rotation-matrix entries are ever read (singular path dropped:
// probability-weighted loss contribution ~1e-7 relative — validated R6)
struct M5 { float m0, m3, m6, m7, m8; };

__device__ __forceinline__ M5 emat5(float x, float y, float z) {
    float cx, sx, cy, sy, cz, sz;
    __sincosf(x, &sx, &cx);
    __sincosf(y, &sy, &cy);
    __sincosf(z, &sz, &cz);
    M5 R;
    R.m0 = cz * cy;
    R.m3 = sz * cy;
    R.m6 = -sy;
    R.m7 = cy * sx;
    R.m8 = cy * cx;
    return R;
}

// euler extraction directly from q = R1 .* P (q-folded form)
__device__ __forceinline__ void extract5(const M5& q,
                                         float& e0, float& e1, float& e2) {
    float sy = sqrtf(fmaf(q.m0, q.m0, q.m3 * q.m3));
    e0 = fast_atan2f(q.m7, q.m8);
    e1 = fast_atan2_posx(-q.m6, sy);
    e2 = fast_atan2f(q.m3, q.m0);
}

__device__ __forceinline__ void cpmul(M5& p, const M5& R) {
    p.m0 *= R.m0; p.m3 *= R.m3; p.m6 *= R.m6; p.m7 *= R.m7; p.m8 *= R.m8;
}

__global__ void __launch_bounds__(TPB, 18)
cycle_loss_kernel(const float* __restrict__ pred, const float* __restrict__ gt,
                  float* __restrict__ out, double scale)
{
    __shared__ float sbuf[2 * ROWS_B * STR + 16];
    const int tid = threadIdx.x;
    const long gbase = (long)blockIdx.x * ROWS_B * ROWF;
    const float4* p4 = (const float4*)(pred + gbase);
    const float4* g4 = (const float4*)(gt   + gbase);

    // ---- phase A stage: floats [0,32) of each row (float4 idx 0..7) ----
    #pragma unroll
    for (int j = tid; j < ROWS_B * 8; j += TPB) {
        int r = j >> 3, c = j & 7;
        float4 v = p4[r * 15 + c];
        float* d = &sbuf[r * STR + 4 * c];
        d[0] = v.x; d[1] = v.y; d[2] = v.z; d[3] = v.w;
        float4 w = g4[r * 15 + c];
        float* e = &sbuf[GTOFF + r * STR + 4 * c];
        e[0] = w.x; e[1] = w.y; e[2] = w.z; e[3] = w.w;
    }
    __syncthreads();

    const float* P = &sbuf[(tid & 1) * GTOFF + (tid >> 1) * STR];

    float acc = 0.0f;
    float v0, v1, v2, c0, c1, c2;
    M5 q;                       // q_i = R1 .* prod_{k<i} R_k ; extraction reads q directly

    // ---- phase A compute: steps 0-4 (uses floats 0..29 only) ----
    {
        // step 0: q_0 = R1
        v0 = P[0]; v1 = P[1]; v2 = P[2];
        {
            float d0 = v0 - __shfl_xor_sync(0xffffffffu, v0, 1);
            float d1 = v1 - __shfl_xor_sync(0xffffffffu, v1, 1);
            float d2 = v2 - __shfl_xor_sync(0xffffffffu, v2, 1);
            acc += d0 * d0 + d1 * d1 + d2 * d2;
        }
        q = emat5(P[9], P[10], P[11]);          // R1
        M5 R1s = q;                              // save R_1 for the step-1 update
        {
            float e0, e1, e2;
            extract5(q, e0, e1, e2);
            float d0 = e0 - __shfl_xor_sync(0xffffffffu, e0, 1);
            float d1 = e1 - __shfl_xor_sync(0xffffffffu, e1, 1);
            float d2 = e2 - __shfl_xor_sync(0xffffffffu, e2, 1);
            acc += d0 * d0 + d1 * d1 + d2 * d2;
        }
        {
            M5 R0 = emat5(P[3], P[4], P[5]);
            cpmul(q, R0);                        // q_1 = R1 .* R0
        }

        // step 1
        v0 = 2.0f * v0; v1 = 2.0f * v1; v2 = 2.0f * v2;
        {
            float d0 = v0 - __shfl_xor_sync(0xffffffffu, v0, 1);
            float d1 = v1 - __shfl_xor_sync(0xffffffffu, v1, 1);
            float d2 = v2 - __shfl_xor_sync(0xffffffffu, v2, 1);
            acc += d0 * d0 + d1 * d1 + d2 * d2;
        }
        c0 = P[6]; c1 = P[7]; c2 = P[8];
        {
            float e0, e1, e2;
            extract5(q, e0, e1, e2);
            float d0 = e0 - __shfl_xor_sync(0xffffffffu, e0, 1);
            float d1 = e1 - __shfl_xor_sync(0xffffffffu, e1, 1);
            float d2 = e2 - __shfl_xor_sync(0xffffffffu, e2, 1);
            acc += d0 * d0 + d1 * d1 + d2 * d2;
        }
        cpmul(q, R1s);                           // q_2 = q_1 .* R_1

        // steps 2-4
        #pragma unroll
        for (int i = 2; i <= 4; i++) {
            const float* S = &P[6 * i];
            v0 = fmaf(2.0f, v0, c0);
            v1 = fmaf(2.0f, v1, c1);
            v2 = fmaf(2.0f, v2, c2);
            {
                float d0 = v0 - __shfl_xor_sync(0xffffffffu, v0, 1);
                float d1 = v1 - __shfl_xor_sync(0xffffffffu, v1, 1);
                float d2 = v2 - __shfl_xor_sync(0xffffffffu, v2, 1);
                acc += d0 * d0 + d1 * d1 + d2 * d2;
            }
            c0 += S[0]; c1 += S[1]; c2 += S[2];
            {
                float e0, e1, e2;
                extract5(q, e0, e1, e2);
                float d0 = e0 - __shfl_xor_sync(0xffffffffu, e0, 1);
                float d1 = e1 - __shfl_xor_sync(0xffffffffu, e1, 1);
                float d2 = e2 - __shfl_xor_sync(0xffffffffu, e2, 1);
                acc += d0 * d0 + d1 * d1 + d2 * d2;
            }
            M5 R = emat5(S[3], S[4], S[5]);
            cpmul(q, R);                         // q_{i+1} = q_i .* R_i
        }
    }
    __syncthreads();

    // ---- phase B stage: floats [28,60) of each row (float4 idx 7..14) ----
    // uniform 8-float4 loop, same shape as phase A; no carry regs needed
    #pragma unroll
    for (int j = tid; j < ROWS_B * 8; j += TPB) {
        int r = j >> 3, c = j & 7;
        float4 v = p4[r * 15 + 7 + c];
        float* d = &sbuf[r * STR + 4 * c];
        d[0] = v.x; d[1] = v.y; d[2] = v.z; d[3] = v.w;
        float4 w = g4[r * 15 + 7 + c];
        float* e = &sbuf[GTOFF + r * STR + 4 * c];
        e[0] = w.x; e[1] = w.y; e[2] = w.z; e[3] = w.w;
    }
    __syncthreads();

    // ---- phase B compute: steps 5-9 (float f at P[f - 28]) ----
    {
        // step 5: t = floats 30,31,32 -> P[2],P[3],P[4]; r = 33,34,35 -> P[5..7]
        v0 = fmaf(2.0f, v0, c0);
        v1 = fmaf(2.0f, v1, c1);
        v2 = fmaf(2.0f, v2, c2);
        {
            float d0 = v0 - __shfl_xor_sync(0xffffffffu, v0, 1);
            float d1 = v1 - __shfl_xor_sync(0xffffffffu, v1, 1);
            float d2 = v2 - __shfl_xor_sync(0xffffffffu, v2, 1);
            acc += d0 * d0 + d1 * d1 + d2 * d2;
        }
        c0 += P[2]; c1 += P[3]; c2 += P[4];
        {
            float e0, e1, e2;
            extract5(q, e0, e1, e2);
            float d0 = e0 - __shfl_xor_sync(0xffffffffu, e0, 1);
            float d1 = e1 - __shfl_xor_sync(0xffffffffu, e1, 1);
            float d2 = e2 - __shfl_xor_sync(0xffffffffu, e2, 1);
            acc += d0 * d0 + d1 * d1 + d2 * d2;
        }
        {
            M5 R = emat5(P[5], P[6], P[7]);
            cpmul(q, R);
        }

        // steps 6-9: float f -> P[f - 28]
        #pragma unroll
        for (int i = 6; i <= 9; i++) {
            const float* S = &P[6 * i - 28];
            v0 = fmaf(2.0f, v0, c0);
            v1 = fmaf(2.0f, v1, c1);
            v2 = fmaf(2.0f, v2, c2);
            {
                float d0 = v0 - __shfl_xor_sync(0xffffffffu, v0, 1);
                float d1 = v1 - __shfl_xor_sync(0xffffffffu, v1, 1);
                float d2 = v2 - __shfl_xor_sync(0xffffffffu, v2, 1);
                acc += d0 * d0 + d1 * d1 + d2 * d2;
            }
            {
                float e0, e1, e2;
                extract5(q, e0, e1, e2);
                float d0 = e0 - __shfl_xor_sync(0xffffffffu, e0, 1);
                float d1 = e1 - __shfl_xor_sync(0xffffffffu, e1, 1);
                float d2 = e2 - __shfl_xor_sync(0xffffffffu, e2, 1);
                acc += d0 * d0 + d1 * d1 + d2 * d2;
            }
            if (i < 9) {
                c0 += S[0]; c1 += S[1]; c2 += S[2];
                M5 R = emat5(S[3], S[4], S[5]);
                cpmul(q, R);
            }
        }
    }

    // ---------------- block reduction ----------------
    #pragma unroll
    for (int o = 16; o > 0; o >>= 1)
        acc += __shfl_down_sync(0xffffffffu, acc, o);

    __shared__ float wsum[TPB / 32];
    if ((tid & 31) == 0) wsum[tid >> 5] = acc;
    __syncthreads();

    __shared__ bool is_last;
    if (tid == 0) {
        float sblk = 0.0f;
        #pragma unroll
        for (int w = 0; w < TPB / 32; w++) sblk += wsum[w];
        g_partials[blockIdx.x] = sblk;
        __threadfence();
        unsigned int c = atomicAdd(&g_count, 1u);
        is_last = (c == gridDim.x - 1);
    }
    __syncthreads();

    // ---------------- last block: deterministic final reduce ----------------
    if (is_last) {
        double sd = 0.0;
        for (int i = tid; i < (int)gridDim.x; i += TPB)
            sd += (double)g_partials[i];
        #pragma unroll
        for (int o = 16; o > 0; o >>= 1)
            sd += __shfl_down_sync(0xffffffffu, sd, o);
        __shared__ double dsum[TPB / 32];
        if ((tid & 31) == 0) dsum[tid >> 5] = sd;
        __syncthreads();
        if (tid == 0) {
            double t = 0.0;
            #pragma unroll
            for (int w = 0; w < TPB / 32; w++) t += dsum[w];
            out[0] = (float)(t * scale);
            g_count = 0;            // reset for next graph replay
        }
    }
}

extern "C" void kernel_launch(void* const* d_in, const int* in_sizes, int n_in,
                              void* d_out, int out_size)
{
    const float* pred = (const float*)d_in[0];
    const float* gt   = (const float*)d_in[1];
    int batch   = in_sizes[0] / ROWF;       // 262144
    int nblocks = batch / ROWS_B;           // 8192

    // loss = sum / (60 * B * B); extra 0.5: both lanes of a pair accumulate
    // the same squared difference.
    double scale = 0.5 / (60.0 * (double)batch * (double)batch);
    cycle_loss_kernel<<<nblocks, TPB>>>(pred, gt, (float*)d_out, scale);
}

// round 17
// speedup vs baseline: 1.2203x; 1.2203x over previous
#include <cuda_runtime.h>
#include <cuda_bf16.h>

#define TPB    128         // 64 rows/block; even lane = pred, odd lane = gt
#define ROWS_B 64
#define ROWF   60
#define STR    33          // smem row stride (odd -> conflict-free)
#define GTOFF  (ROWS_B * STR + 16)   // +16: lane pairs hit disjoint bank halves
#define NSTEP  10

__device__ float        g_partials[8192];
__device__ unsigned int g_count = 0;

// ---------------------------------------------------------------------------
// fast atan2: degree-7 minimax, max abs err ~6e-4 rad. Validated R12-R15:
// loss rel_err bit-identical (7.56e-7) vs degree-9 — far under the 1e-3 gate.
// ---------------------------------------------------------------------------
__device__ __forceinline__ float atan_core(float a) {   // a in [0,1]
    float s  = a * a;
    float r  = fmaf(0.079331f, s, -0.288679f);
    r = fmaf(r, s, 0.995354f);
    return a * r;
}

__device__ __forceinline__ float fast_atan2f(float y, float x) {
    float ax = fabsf(x), ay = fabsf(y);
    float mx = fmaxf(ax, ay);
    float mn = fminf(ax, ay);
    float r  = atan_core(__fdividef(mn, mx));
    if (ay > ax)   r = 1.57079632679489662f - r;
    if (x < 0.0f)  r = 3.14159265358979323f - r;
    return copysignf(r, y);
}

// x >= 0 guaranteed
__device__ __forceinline__ float fast_atan2_posx(float y, float x) {
    float ay = fabsf(y);
    float mx = fmaxf(x, ay);
    float mn = fminf(x, ay);
    float r  = atan_core(__fdividef(mn, mx));
    if (ay > x) r = 1.57079632679489662f - r;
    return copysignf(r, y);
}

// only 5 rotation-matrix entries are ever read (singular path dropped:
// probability-weighted loss contribution ~1e-7 relative — validated R6)
struct M5 { float m0, m3, m6, m7, m8; };

__device__ __forceinline__ M5 emat5(float x, float y, float z) {
    float cx, sx, cy, sy, cz, sz;
    __sincosf(x, &sx, &cx);
    __sincosf(y, &sy, &cy);
    __sincosf(z, &sz, &cz);
    M5 R;
    R.m0 = cz * cy;
    R.m3 = sz * cy;
    R.m6 = -sy;
    R.m7 = cy * sx;
    R.m8 = cy * cx;
    return R;
}

// euler extraction directly from q = R1 .* P (q-folded form)
__device__ __forceinline__ void extract5(const M5& q,
                                         float& e0, float& e1, float& e2) {
    float sy = sqrtf(fmaf(q.m0, q.m0, q.m3 * q.m3));
    e0 = fast_atan2f(q.m7, q.m8);
    e1 = fast_atan2_posx(-q.m6, sy);
    e2 = fast_atan2f(q.m3, q.m0);
}

__device__ __forceinline__ void cpmul(M5& p, const M5& R) {
    p.m0 *= R.m0; p.m3 *= R.m3; p.m6 *= R.m6; p.m7 *= R.m7; p.m8 *= R.m8;
}

__global__ void __launch_bounds__(TPB, 9)
cycle_loss_kernel(const float* __restrict__ pred, const float* __restrict__ gt,
                  float* __restrict__ out, double scale)
{
    __shared__ float sbuf[2 * ROWS_B * STR + 16];
    const int tid = threadIdx.x;
    const long gbase = (long)blockIdx.x * ROWS_B * ROWF;
    const float4* p4 = (const float4*)(pred + gbase);
    const float4* g4 = (const float4*)(gt   + gbase);

    // ---- phase A stage: floats [0,32) of each row (8 float4) ----
    #pragma unroll
    for (int j = tid; j < ROWS_B * 8; j += TPB) {
        int r = j >> 3, c = j & 7;
        float4 v = p4[r * 15 + c];
        float* d = &sbuf[r * STR + 4 * c];
        d[0] = v.x; d[1] = v.y; d[2] = v.z; d[3] = v.w;
        float4 w = g4[r * 15 + c];
        float* e = &sbuf[GTOFF + r * STR + 4 * c];
        e[0] = w.x; e[1] = w.y; e[2] = w.z; e[3] = w.w;
    }
    __syncthreads();

    const float* P = &sbuf[(tid & 1) * GTOFF + (tid >> 1) * STR];

    float acc = 0.0f;
    float v0, v1, v2, c0, c1, c2;
    M5 q;                       // q_i = R1 .* prod_{k<i} R_k ; extraction reads q directly

    // ---- phase A compute: steps 0-4 ----
    {
        // step 0: q_0 = R1
        v0 = P[0]; v1 = P[1]; v2 = P[2];
        {
            float d0 = v0 - __shfl_xor_sync(0xffffffffu, v0, 1);
            float d1 = v1 - __shfl_xor_sync(0xffffffffu, v1, 1);
            float d2 = v2 - __shfl_xor_sync(0xffffffffu, v2, 1);
            acc += d0 * d0 + d1 * d1 + d2 * d2;
        }
        q = emat5(P[9], P[10], P[11]);          // R1
        M5 R1s = q;                              // save R_1 for the step-1 update
        {
            float e0, e1, e2;
            extract5(q, e0, e1, e2);
            float d0 = e0 - __shfl_xor_sync(0xffffffffu, e0, 1);
            float d1 = e1 - __shfl_xor_sync(0xffffffffu, e1, 1);
            float d2 = e2 - __shfl_xor_sync(0xffffffffu, e2, 1);
            acc += d0 * d0 + d1 * d1 + d2 * d2;
        }
        {
            M5 R0 = emat5(P[3], P[4], P[5]);
            cpmul(q, R0);                        // q_1 = R1 .* R0
        }

        // step 1
        v0 = 2.0f * v0; v1 = 2.0f * v1; v2 = 2.0f * v2;
        {
            float d0 = v0 - __shfl_xor_sync(0xffffffffu, v0, 1);
            float d1 = v1 - __shfl_xor_sync(0xffffffffu, v1, 1);
            float d2 = v2 - __shfl_xor_sync(0xffffffffu, v2, 1);
            acc += d0 * d0 + d1 * d1 + d2 * d2;
        }
        c0 = P[6]; c1 = P[7]; c2 = P[8];
        {
            float e0, e1, e2;
            extract5(q, e0, e1, e2);
            float d0 = e0 - __shfl_xor_sync(0xffffffffu, e0, 1);
            float d1 = e1 - __shfl_xor_sync(0xffffffffu, e1, 1);
            float d2 = e2 - __shfl_xor_sync(0xffffffffu, e2, 1);
            acc += d0 * d0 + d1 * d1 + d2 * d2;
        }
        cpmul(q, R1s);                           // q_2 = q_1 .* R_1

        // steps 2-4
        #pragma unroll
        for (int i = 2; i <= 4; i++) {
            const float* S = &P[6 * i];
            v0 = fmaf(2.0f, v0, c0);
            v1 = fmaf(2.0f, v1, c1);
            v2 = fmaf(2.0f, v2, c2);
            {
                float d0 = v0 - __shfl_xor_sync(0xffffffffu, v0, 1);
                float d1 = v1 - __shfl_xor_sync(0xffffffffu, v1, 1);
                float d2 = v2 - __shfl_xor_sync(0xffffffffu, v2, 1);
                acc += d0 * d0 + d1 * d1 + d2 * d2;
            }
            c0 += S[0]; c1 += S[1]; c2 += S[2];
            {
                float e0, e1, e2;
                extract5(q, e0, e1, e2);
                float d0 = e0 - __shfl_xor_sync(0xffffffffu, e0, 1);
                float d1 = e1 - __shfl_xor_sync(0xffffffffu, e1, 1);
                float d2 = e2 - __shfl_xor_sync(0xffffffffu, e2, 1);
                acc += d0 * d0 + d1 * d1 + d2 * d2;
            }
            M5 R = emat5(S[3], S[4], S[5]);
            cpmul(q, R);                         // q_{i+1} = q_i .* R_i
        }
    }

    // carry floats 30,31 (t0,t1 of step 5) across the restage
    float s30 = P[30], s31 = P[31];
    __syncthreads();

    // ---- phase B stage: floats [32,60) of each row (7 float4) ----
    #pragma unroll
    for (int j = tid; j < ROWS_B * 8; j += TPB) {
        int r = j >> 3, c = j & 7;
        if (c < 7) {
            float4 v = p4[r * 15 + 8 + c];
            float* d = &sbuf[r * STR + 4 * c];
            d[0] = v.x; d[1] = v.y; d[2] = v.z; d[3] = v.w;
            float4 w = g4[r * 15 + 8 + c];
            float* e = &sbuf[GTOFF + r * STR + 4 * c];
            e[0] = w.x; e[1] = w.y; e[2] = w.z; e[3] = w.w;
        }
    }
    __syncthreads();

    // ---- phase B compute: steps 5-9 (buffer holds floats 32..59 at 0..27) ----
    {
        // step 5: t = (s30, s31, P[0]); r = (P[1], P[2], P[3])
        v0 = fmaf(2.0f, v0, c0);
        v1 = fmaf(2.0f, v1, c1);
        v2 = fmaf(2.0f, v2, c2);
        {
            float d0 = v0 - __shfl_xor_sync(0xffffffffu, v0, 1);
            float d1 = v1 - __shfl_xor_sync(0xffffffffu, v1, 1);
            float d2 = v2 - __shfl_xor_sync(0xffffffffu, v2, 1);
            acc += d0 * d0 + d1 * d1 + d2 * d2;
        }
        c0 += s30; c1 += s31; c2 += P[0];
        {
            float e0, e1, e2;
            extract5(q, e0, e1, e2);
            float d0 = e0 - __shfl_xor_sync(0xffffffffu, e0, 1);
            float d1 = e1 - __shfl_xor_sync(0xffffffffu, e1, 1);
            float d2 = e2 - __shfl_xor_sync(0xffffffffu, e2, 1);
            acc += d0 * d0 + d1 * d1 + d2 * d2;
        }
        {
            M5 R = emat5(P[1], P[2], P[3]);
            cpmul(q, R);
        }

        // steps 6-9: float f -> P[f - 32]
        #pragma unroll
        for (int i = 6; i <= 9; i++) {
            const float* S = &P[6 * i - 32];
            v0 = fmaf(2.0f, v0, c0);
            v1 = fmaf(2.0f, v1, c1);
            v2 = fmaf(2.0f, v2, c2);
            {
                float d0 = v0 - __shfl_xor_sync(0xffffffffu, v0, 1);
                float d1 = v1 - __shfl_xor_sync(0xffffffffu, v1, 1);
                float d2 = v2 - __shfl_xor_sync(0xffffffffu, v2, 1);
                acc += d0 * d0 + d1 * d1 + d2 * d2;
            }
            {
                float e0, e1, e2;
                extract5(q, e0, e1, e2);
                float d0 = e0 - __shfl_xor_sync(0xffffffffu, e0, 1);
                float d1 = e1 - __shfl_xor_sync(0xffffffffu, e1, 1);
                float d2 = e2 - __shfl_xor_sync(0xffffffffu, e2, 1);
                acc += d0 * d0 + d1 * d1 + d2 * d2;
            }
            if (i < 9) {
                c0 += S[0]; c1 += S[1]; c2 += S[2];
                M5 R = emat5(S[3], S[4], S[5]);
                cpmul(q, R);
            }
        }
    }

    // ---------------- block reduction ----------------
    #pragma unroll
    for (int o = 16; o > 0; o >>= 1)
        acc += __shfl_down_sync(0xffffffffu, acc, o);

    __shared__ float wsum[TPB / 32];
    if ((tid & 31) == 0) wsum[tid >> 5] = acc;
    __syncthreads();

    __shared__ bool is_last;
    if (tid == 0) {
        float sblk = 0.0f;
        #pragma unroll
        for (int w = 0; w < TPB / 32; w++) sblk += wsum[w];
        g_partials[blockIdx.x] = sblk;
        __threadfence();
        unsigned int c = atomicAdd(&g_count, 1u);
        is_last = (c == gridDim.x - 1);
    }
    __syncthreads();

    // ---------------- last block: deterministic final reduce ----------------
    if (is_last) {
        double sd = 0.0;
        for (int i = tid; i < (int)gridDim.x; i += TPB)
            sd += (double)g_partials[i];
        #pragma unroll
        for (int o = 16; o > 0; o >>= 1)
            sd += __shfl_down_sync(0xffffffffu, sd, o);
        __shared__ double dsum[TPB / 32];
        if ((tid & 31) == 0) dsum[tid >> 5] = sd;
        __syncthreads();
        if (tid == 0) {
            double t = 0.0;
            #pragma unroll
            for (int w = 0; w < TPB / 32; w++) t += dsum[w];
            out[0] = (float)(t * scale);
            g_count = 0;            // reset for next graph replay
        }
    }
}

extern "C" void kernel_launch(void* const* d_in, const int* in_sizes, int n_in,
                              void* d_out, int out_size)
{
    const float* pred = (const float*)d_in[0];
    const float* gt   = (const float*)d_in[1];
    int batch   = in_sizes[0] / ROWF;       // 262144
    int nblocks = batch / ROWS_B;           // 4096

    // loss = sum / (60 * B * B); extra 0.5: both lanes of a pair accumulate
    // the same squared difference.
    double scale = 0.5 / (60.0 * (double)batch * (double)batch);
    cycle_loss_kernel<<<nblocks, TPB>>>(pred, gt, (float*)d_out, scale);
}